// round 4
// baseline (speedup 1.0000x reference)
#include <cuda_runtime.h>
#include <cstdint>

#define N_ATOM 50000
#define M_NBR  12
#define NM_TOT 600000
#define F_DIM  128
#define FAN_IN 320
#define EPS    1e-5f
#define CH     25

typedef unsigned long long ull;

#define UNPACK_F32X2(lo, hi, in) \
    asm("mov.b64 {%0, %1}, %2;" : "=f"(lo), "=f"(hi) : "l"(in))
#define FMA_F32X2(acc, a, b) \
    asm("fma.rn.f32x2 %0, %1, %2, %0;" : "+l"(acc) : "l"(a), "l"(b))

// ---------------- scratch (static __device__, no allocation) ----------------
__device__ __align__(16) float g_SA[(size_t)N_ATOM * 512];      // [n][0:256)=S, [256:512)=A
__device__ __align__(16) float g_gated[(size_t)NM_TOT * 256];   // pre-BN gated
__device__ __align__(16) float g_nbr[(size_t)N_ATOM * F_DIM];   // nbr_sumed
__device__ float g_stats1[512];
__device__ float g_stats2[256];
__device__ float g_bn1[512];
__device__ float g_bn2[256];
__device__ int   g_idx32[NM_TOT];
__device__ int   g_is64;

__device__ __forceinline__ float softplusf(float x) {
    return fmaxf(x, 0.f) + log1pf(__expf(-fabsf(x)));
}
__device__ __forceinline__ float sigmoidf(float x) {
    return 1.f / (1.f + __expf(-x));
}

// ---------------- k_detect ---------------------------------------------------
__global__ void k_detect(const int* __restrict__ raw) {
    __shared__ int any;
    if (threadIdx.x == 0) any = 0;
    __syncthreads();
    if (raw[threadIdx.x * 2 + 1] != 0) atomicOr(&any, 1);
    __syncthreads();
    if (threadIdx.x == 0) g_is64 = any ? 0 : 1;
}

// ---------------- k_convert --------------------------------------------------
__global__ void k_convert(const int* __restrict__ raw) {
    int i = blockIdx.x * blockDim.x + threadIdx.x;
    if (i < NM_TOT) g_idx32[i] = g_is64 ? raw[2 * i] : raw[i];
    if (i < 512) g_stats1[i] = 0.f;
    if (i < 256) g_stats2[i] = 0.f;
}

// =============== shared GEMM micro-kernel pieces ============================
// 256 threads: tx=tid&15 (8 cols: tx*4+{0..3}, 64+tx*4+{0..3})
//              ty=tid>>4 (8 rows: ty*4+{0..3}, 64+ty*4+{0..3})
// Xs2[k][2r](dup)  Ws[k][f].  acc[i][j]: i=row(8), j=colpair(4) packed f32x2.

// ---------------- k1: [S|A] = atom @ [W_self|W_nbr]^T  (50000x512, K=128) ---
__global__ __launch_bounds__(256) void k_gemm_sa(const float* __restrict__ atom,
                                                 const float* __restrict__ W) {
    __shared__ __align__(16) float Xs2[64][256];
    __shared__ __align__(16) float Ws[64][128];
    const int tid = threadIdx.x;
    const int tx = tid & 15, ty = tid >> 4;
    const int fbase = blockIdx.x * 128;     // 0,128,256,384
    const int row0  = blockIdx.y * 128;
    const int wfbase = (fbase < 256) ? fbase : fbase - 256;
    const int wkoff  = (fbase < 256) ? 0 : 128;

    ull acc[8][4];
#pragma unroll
    for (int i = 0; i < 8; i++)
#pragma unroll
        for (int j = 0; j < 4; j++) acc[i][j] = 0ULL;

    for (int kc = 0; kc < 128; kc += 64) {
        for (int t = tid; t < 2048; t += 256) {
            int r = t & 127, kq = t >> 7;          // kq 0..15
            int gr = row0 + r; if (gr >= N_ATOM) gr = N_ATOM - 1;
            float4 v = *(const float4*)(atom + (size_t)gr * 128 + kc + kq * 4);
            *(float2*)&Xs2[kq * 4 + 0][2 * r] = make_float2(v.x, v.x);
            *(float2*)&Xs2[kq * 4 + 1][2 * r] = make_float2(v.y, v.y);
            *(float2*)&Xs2[kq * 4 + 2][2 * r] = make_float2(v.z, v.z);
            *(float2*)&Xs2[kq * 4 + 3][2 * r] = make_float2(v.w, v.w);
        }
        for (int t = tid; t < 2048; t += 256) {
            int fl = t & 127, kq = t >> 7;
            float4 v = *(const float4*)(W + (size_t)(wfbase + fl) * FAN_IN + wkoff + kc + kq * 4);
            Ws[kq * 4 + 0][fl] = v.x; Ws[kq * 4 + 1][fl] = v.y;
            Ws[kq * 4 + 2][fl] = v.z; Ws[kq * 4 + 3][fl] = v.w;
        }
        __syncthreads();
#pragma unroll 4
        for (int k = 0; k < 64; k++) {
            ulonglong2 A0 = *(ulonglong2*)&Xs2[k][8 * ty];
            ulonglong2 A1 = *(ulonglong2*)&Xs2[k][8 * ty + 4];
            ulonglong2 A2 = *(ulonglong2*)&Xs2[k][128 + 8 * ty];
            ulonglong2 A3 = *(ulonglong2*)&Xs2[k][128 + 8 * ty + 4];
            ulonglong2 B0 = *(ulonglong2*)&Ws[k][tx * 4];
            ulonglong2 B1 = *(ulonglong2*)&Ws[k][64 + tx * 4];
            ull aa[8] = {A0.x, A0.y, A1.x, A1.y, A2.x, A2.y, A3.x, A3.y};
#pragma unroll
            for (int i = 0; i < 8; i++) {
                FMA_F32X2(acc[i][0], aa[i], B0.x);
                FMA_F32X2(acc[i][1], aa[i], B0.y);
                FMA_F32X2(acc[i][2], aa[i], B1.x);
                FMA_F32X2(acc[i][3], aa[i], B1.y);
            }
        }
        __syncthreads();
    }
#pragma unroll
    for (int i = 0; i < 8; i++) {
        int r = (i < 4) ? (ty * 4 + i) : (64 + ty * 4 + (i - 4));
        int gr = row0 + r;
        if (gr >= N_ATOM) continue;
        float e[8];
        UNPACK_F32X2(e[0], e[1], acc[i][0]);
        UNPACK_F32X2(e[2], e[3], acc[i][1]);
        UNPACK_F32X2(e[4], e[5], acc[i][2]);
        UNPACK_F32X2(e[6], e[7], acc[i][3]);
        *(float4*)(g_SA + (size_t)gr * 512 + fbase + tx * 4) =
            make_float4(e[0], e[1], e[2], e[3]);
        *(float4*)(g_SA + (size_t)gr * 512 + fbase + 64 + tx * 4) =
            make_float4(e[4], e[5], e[6], e[7]);
    }
}

// ---------------- k2: E = nbr @ W_edge^T, fused gated + BN1 stats -----------
__global__ __launch_bounds__(256) void k_gemm_gate(const float* __restrict__ nbr,
                                                   const float* __restrict__ W,
                                                   const float* __restrict__ bias) {
    __shared__ __align__(16) float Xs2[64][256];
    __shared__ __align__(16) float Ws[64][128];
    __shared__ float s_stat[256];
    const int tid = threadIdx.x;
    const int tx = tid & 15, ty = tid >> 4;
    const int fbase = blockIdx.x * 128;   // 0 or 128
    const int row0  = blockIdx.y * 128;

    ull acc[8][4];
#pragma unroll
    for (int i = 0; i < 8; i++)
#pragma unroll
        for (int j = 0; j < 4; j++) acc[i][j] = 0ULL;

    for (int t = tid; t < 2048; t += 256) {
        int r = t & 127, kq = t >> 7;
        int gr = row0 + r; if (gr >= NM_TOT) gr = NM_TOT - 1;
        float4 v = *(const float4*)(nbr + (size_t)gr * 64 + kq * 4);
        *(float2*)&Xs2[kq * 4 + 0][2 * r] = make_float2(v.x, v.x);
        *(float2*)&Xs2[kq * 4 + 1][2 * r] = make_float2(v.y, v.y);
        *(float2*)&Xs2[kq * 4 + 2][2 * r] = make_float2(v.z, v.z);
        *(float2*)&Xs2[kq * 4 + 3][2 * r] = make_float2(v.w, v.w);
    }
    for (int t = tid; t < 2048; t += 256) {
        int fl = t & 127, kq = t >> 7;
        float4 v = *(const float4*)(W + (size_t)(fbase + fl) * FAN_IN + 256 + kq * 4);
        Ws[kq * 4 + 0][fl] = v.x; Ws[kq * 4 + 1][fl] = v.y;
        Ws[kq * 4 + 2][fl] = v.z; Ws[kq * 4 + 3][fl] = v.w;
    }
    __syncthreads();

#pragma unroll 4
    for (int k = 0; k < 64; k++) {
        ulonglong2 A0 = *(ulonglong2*)&Xs2[k][8 * ty];
        ulonglong2 A1 = *(ulonglong2*)&Xs2[k][8 * ty + 4];
        ulonglong2 A2 = *(ulonglong2*)&Xs2[k][128 + 8 * ty];
        ulonglong2 A3 = *(ulonglong2*)&Xs2[k][128 + 8 * ty + 4];
        ulonglong2 B0 = *(ulonglong2*)&Ws[k][tx * 4];
        ulonglong2 B1 = *(ulonglong2*)&Ws[k][64 + tx * 4];
        ull aa[8] = {A0.x, A0.y, A1.x, A1.y, A2.x, A2.y, A3.x, A3.y};
#pragma unroll
        for (int i = 0; i < 8; i++) {
            FMA_F32X2(acc[i][0], aa[i], B0.x);
            FMA_F32X2(acc[i][1], aa[i], B0.y);
            FMA_F32X2(acc[i][2], aa[i], B1.x);
            FMA_F32X2(acc[i][3], aa[i], B1.y);
        }
    }
    __syncthreads();

    // epilogue: gated = S + b + msk*(A[idx] + E); store + BN1 stats
    s_stat[tid] = 0.f;
    __syncthreads();

    float4 bia0 = *(const float4*)(bias + fbase + tx * 4);
    float4 bia1 = *(const float4*)(bias + fbase + 64 + tx * 4);
    float sums[8], sqs[8];
#pragma unroll
    for (int q = 0; q < 8; q++) { sums[q] = 0.f; sqs[q] = 0.f; }

#pragma unroll
    for (int i = 0; i < 8; i++) {
        int r = (i < 4) ? (ty * 4 + i) : (64 + ty * 4 + (i - 4));
        int nm = row0 + r;
        if (nm >= NM_TOT) continue;
        int n = nm / 12;
        int j = g_idx32[nm];
        float msk = (j != 0) ? 1.f : 0.f;
        float e[8];
        UNPACK_F32X2(e[0], e[1], acc[i][0]);
        UNPACK_F32X2(e[2], e[3], acc[i][1]);
        UNPACK_F32X2(e[4], e[5], acc[i][2]);
        UNPACK_F32X2(e[6], e[7], acc[i][3]);
#pragma unroll
        for (int cg = 0; cg < 2; cg++) {
            int col = fbase + cg * 64 + tx * 4;
            float4 s4 = *(const float4*)(g_SA + (size_t)n * 512 + col);
            float4 a4 = *(const float4*)(g_SA + (size_t)j * 512 + 256 + col);
            float4 bb4 = cg ? bia1 : bia0;
            float g0 = s4.x + bb4.x + msk * (a4.x + e[cg * 4 + 0]);
            float g1 = s4.y + bb4.y + msk * (a4.y + e[cg * 4 + 1]);
            float g2 = s4.z + bb4.z + msk * (a4.z + e[cg * 4 + 2]);
            float g3 = s4.w + bb4.w + msk * (a4.w + e[cg * 4 + 3]);
            *(float4*)(g_gated + (size_t)nm * 256 + col) = make_float4(g0, g1, g2, g3);
            sums[cg * 4 + 0] += g0; sqs[cg * 4 + 0] += g0 * g0;
            sums[cg * 4 + 1] += g1; sqs[cg * 4 + 1] += g1 * g1;
            sums[cg * 4 + 2] += g2; sqs[cg * 4 + 2] += g2 * g2;
            sums[cg * 4 + 3] += g3; sqs[cg * 4 + 3] += g3 * g3;
        }
    }
#pragma unroll
    for (int q = 0; q < 8; q++) {
        int lc = (q >> 2) * 64 + tx * 4 + (q & 3);
        atomicAdd(&s_stat[lc], sums[q]);
        atomicAdd(&s_stat[128 + lc], sqs[q]);
    }
    __syncthreads();
    if (tid < 128) {
        atomicAdd(&g_stats1[fbase + tid],       s_stat[tid]);
        atomicAdd(&g_stats1[256 + fbase + tid], s_stat[128 + tid]);
    }
}

// ---------------- k3: finalize BN1 affine ------------------------------------
__global__ void k_fin1(const float* __restrict__ gamma1, const float* __restrict__ beta1) {
    int f = threadIdx.x;  // 256
    float inv = 1.f / (float)NM_TOT;
    float mean = g_stats1[f] * inv;
    float var  = g_stats1[256 + f] * inv - mean * mean;
    float sc = gamma1[f] * rsqrtf(var + EPS);
    g_bn1[f] = sc;
    g_bn1[256 + f] = beta1[f] - mean * sc;
}

// ---------------- k4: gate + sum over M + BN2 stats --------------------------
__global__ __launch_bounds__(128) void k_reduce() {
    const int f = threadIdx.x;
    const int n0 = blockIdx.x * CH;
    const float sc_f = g_bn1[f],        sh_f = g_bn1[256 + f];
    const float sc_c = g_bn1[128 + f],  sh_c = g_bn1[256 + 128 + f];
    float bs = 0.f, bq = 0.f;
    for (int n = n0; n < n0 + CH; n++) {
        float acc = 0.f;
#pragma unroll
        for (int m = 0; m < 12; m++) {
            int nm = n * 12 + m;
            int j = g_idx32[nm];
            if (j != 0) {
                float gf = g_gated[(size_t)nm * 256 + f]       * sc_f + sh_f;
                float gc = g_gated[(size_t)nm * 256 + 128 + f] * sc_c + sh_c;
                acc += sigmoidf(gf) * softplusf(gc);
            }
        }
        g_nbr[(size_t)n * 128 + f] = acc;
        bs += acc; bq += acc * acc;
    }
    atomicAdd(&g_stats2[f],       bs);
    atomicAdd(&g_stats2[128 + f], bq);
}

// ---------------- k5: finalize BN2 affine ------------------------------------
__global__ void k_fin2(const float* __restrict__ gamma2, const float* __restrict__ beta2) {
    int f = threadIdx.x;  // 128
    float inv = 1.f / (float)N_ATOM;
    float mean = g_stats2[f] * inv;
    float var  = g_stats2[128 + f] * inv - mean * mean;
    float sc = gamma2[f] * rsqrtf(var + EPS);
    g_bn2[f] = sc;
    g_bn2[128 + f] = beta2[f] - mean * sc;
}

// ---------------- k6: out = softplus(atom + BN2(nbr_sumed)) ------------------
__global__ void k_out(const float* __restrict__ atom, float* __restrict__ out) {
    int i = blockIdx.x * blockDim.x + threadIdx.x;
    if (i < N_ATOM * 128) {
        int f = i & 127;
        float v = atom[i] + g_nbr[i] * g_bn2[f] + g_bn2[128 + f];
        out[i] = softplusf(v);
    }
}

// ---------------- launch ------------------------------------------------------
extern "C" void kernel_launch(void* const* d_in, const int* in_sizes, int n_in,
                              void* d_out, int out_size) {
    const float* atom   = (const float*)d_in[0];
    const float* nbr    = (const float*)d_in[1];
    const int*   idxraw = (const int*)d_in[2];
    const float* W      = (const float*)d_in[3];
    const float* b      = (const float*)d_in[4];
    const float* gamma1 = (const float*)d_in[5];
    const float* beta1  = (const float*)d_in[6];
    const float* gamma2 = (const float*)d_in[7];
    const float* beta2  = (const float*)d_in[8];
    float* out = (float*)d_out;

    k_detect<<<1, 256>>>(idxraw);
    k_convert<<<(NM_TOT + 255) / 256, 256>>>(idxraw);
    k_gemm_sa<<<dim3(4, (N_ATOM + 127) / 128), 256>>>(atom, W);
    k_gemm_gate<<<dim3(2, (NM_TOT + 127) / 128), 256>>>(nbr, W, b);
    k_fin1<<<1, 256>>>(gamma1, beta1);
    k_reduce<<<N_ATOM / CH, 128>>>();
    k_fin2<<<1, 128>>>(gamma2, beta2);
    k_out<<<(N_ATOM * 128 + 255) / 256, 256>>>(atom, out);
}

// round 5
// speedup vs baseline: 1.5943x; 1.5943x over previous
#include <cuda_runtime.h>
#include <cstdint>

#define N_ATOM 50000
#define M_NBR  12
#define NM_TOT 600000
#define F_DIM  128
#define FAN_IN 320
#define EPS    1e-5f
#define CH     25

typedef unsigned long long ull;

#define PACK_F32X2(out, lo, hi) \
    asm("mov.b64 %0, {%1, %2};" : "=l"(out) : "f"(lo), "f"(hi))
#define UNPACK_F32X2(lo, hi, in) \
    asm("mov.b64 {%0, %1}, %2;" : "=f"(lo), "=f"(hi) : "l"(in))
#define FMA_F32X2(acc, a, b) \
    asm("fma.rn.f32x2 %0, %1, %2, %0;" : "+l"(acc) : "l"(a), "l"(b))

// ---------------- scratch ----------------------------------------------------
__device__ __align__(16) float g_SA[(size_t)N_ATOM * 512];      // [n][0:256)=S, [256:512)=A
__device__ __align__(16) float g_gated[(size_t)NM_TOT * 256];
__device__ __align__(16) float g_nbr[(size_t)N_ATOM * F_DIM];
__device__ float g_stats1[512];
__device__ float g_stats2[256];
__device__ float g_bn1[512];
__device__ float g_bn2[256];
__device__ int   g_idx32[NM_TOT];
__device__ int   g_is64;

__device__ __forceinline__ float softplusf(float x) {
    return fmaxf(x, 0.f) + log1pf(__expf(-fabsf(x)));
}
__device__ __forceinline__ float sigmoidf(float x) {
    return 1.f / (1.f + __expf(-x));
}

// ---------------- k_detect ---------------------------------------------------
__global__ void k_detect(const int* __restrict__ raw) {
    __shared__ int any;
    if (threadIdx.x == 0) any = 0;
    __syncthreads();
    if (raw[threadIdx.x * 2 + 1] != 0) atomicOr(&any, 1);
    __syncthreads();
    if (threadIdx.x == 0) g_is64 = any ? 0 : 1;
}

// ---------------- k_convert --------------------------------------------------
__global__ void k_convert(const int* __restrict__ raw) {
    int i = blockIdx.x * blockDim.x + threadIdx.x;
    if (i < NM_TOT) g_idx32[i] = g_is64 ? raw[2 * i] : raw[i];
    if (i < 512) g_stats1[i] = 0.f;
    if (i < 256) g_stats2[i] = 0.f;
}

// ---------------- k1: [S|A] = atom @ [W_self|W_nbr]^T (R3-proven scalar) -----
__global__ __launch_bounds__(256) void k_gemm_sa(const float* __restrict__ atom,
                                                 const float* __restrict__ W) {
    __shared__ float Xs[64][64];
    __shared__ float Ws[64][128];
    const int tid = threadIdx.x;
    const int tx = tid & 31, ty = tid >> 5;
    const int fbase = blockIdx.x * 128;
    const int row0  = blockIdx.y * 64;
    const int wfbase = (blockIdx.x < 2) ? fbase : fbase - 256;
    const int wkoff  = (blockIdx.x < 2) ? 0 : 128;

    float c[8][4];
#pragma unroll
    for (int i = 0; i < 8; i++)
#pragma unroll
        for (int j = 0; j < 4; j++) c[i][j] = 0.f;

    for (int kc = 0; kc < 128; kc += 64) {
        for (int t = tid; t < 64 * 16; t += 256) {
            int r = t >> 4, kq = t & 15;
            int gr = row0 + r;
            float4 v = make_float4(0.f, 0.f, 0.f, 0.f);
            if (gr < N_ATOM)
                v = *(const float4*)(atom + (size_t)gr * 128 + kc + kq * 4);
            *(float4*)&Xs[r][kq * 4] = v;
        }
        for (int t = tid; t < 128 * 16; t += 256) {
            int fl = t & 127, kq = t >> 7;
            float4 v = *(const float4*)(W + (size_t)(wfbase + fl) * FAN_IN + wkoff + kc + kq * 4);
            Ws[kq * 4 + 0][fl] = v.x; Ws[kq * 4 + 1][fl] = v.y;
            Ws[kq * 4 + 2][fl] = v.z; Ws[kq * 4 + 3][fl] = v.w;
        }
        __syncthreads();
#pragma unroll 8
        for (int k = 0; k < 64; k++) {
            float4 b = *(float4*)&Ws[k][tx * 4];
#pragma unroll
            for (int i = 0; i < 8; i++) {
                float a = Xs[ty * 8 + i][k];
                c[i][0] += a * b.x; c[i][1] += a * b.y;
                c[i][2] += a * b.z; c[i][3] += a * b.w;
            }
        }
        __syncthreads();
    }
#pragma unroll
    for (int i = 0; i < 8; i++) {
        int gr = row0 + ty * 8 + i;
        if (gr < N_ATOM)
            *(float4*)(g_SA + (size_t)gr * 512 + fbase + tx * 4) =
                make_float4(c[i][0], c[i][1], c[i][2], c[i][3]);
    }
}

// ---------------- k2: E = nbr @ W_edge^T, fused gated + BN1 stats ------------
// BM=128 rows, BN=64 cols, grid (4, 4688), 256 threads, 3 CTAs/SM target.
// Thread tile: 8 rows (ty*8..+7) x 4 cols (tx*4..+3), row-paired f32x2 lanes:
// acc[p][c] = (rows ty*8+2p, ty*8+2p+1) for col fbase+tx*4+c.
__global__ __launch_bounds__(256, 3) void k_gemm_gate(const float* __restrict__ nbr,
                                                      const float* __restrict__ W,
                                                      const float* __restrict__ bias) {
    __shared__ __align__(16) float Xs[32][128];   // [k][row]
    __shared__ __align__(16) float Ws[32][64];    // [k][f]
    __shared__ float s_stat[128];                 // sum[64], sumsq[64]
    const int tid = threadIdx.x;
    const int tx = tid & 15, ty = tid >> 4;
    const int fbase = blockIdx.x * 64;            // 0,64,128,192
    const int row0  = blockIdx.y * 128;

    ull acc[4][4];
#pragma unroll
    for (int p = 0; p < 4; p++)
#pragma unroll
        for (int c = 0; c < 4; c++) acc[p][c] = 0ULL;

    for (int kc = 0; kc < 64; kc += 32) {
        // X: 128 rows x 32 k, transposed into Xs[k][r]
        for (int t = tid; t < 1024; t += 256) {
            int r = t & 127, kq = t >> 7;          // kq 0..7
            int gr = row0 + r; if (gr >= NM_TOT) gr = NM_TOT - 1;
            float4 v = *(const float4*)(nbr + (size_t)gr * 64 + kc + kq * 4);
            Xs[kq * 4 + 0][r] = v.x; Xs[kq * 4 + 1][r] = v.y;
            Xs[kq * 4 + 2][r] = v.z; Xs[kq * 4 + 3][r] = v.w;
        }
        // W: 64 f x 32 k
        for (int t = tid; t < 512; t += 256) {
            int fl = t & 63, kq = t >> 6;          // kq 0..7
            float4 v = *(const float4*)(W + (size_t)(fbase + fl) * FAN_IN + 256 + kc + kq * 4);
            Ws[kq * 4 + 0][fl] = v.x; Ws[kq * 4 + 1][fl] = v.y;
            Ws[kq * 4 + 2][fl] = v.z; Ws[kq * 4 + 3][fl] = v.w;
        }
        __syncthreads();
#pragma unroll 8
        for (int k = 0; k < 32; k++) {
            ulonglong2 A01 = *(ulonglong2*)&Xs[k][ty * 8];       // (r0,r1),(r2,r3)
            ulonglong2 A23 = *(ulonglong2*)&Xs[k][ty * 8 + 4];   // (r4,r5),(r6,r7)
            float4 Bv = *(float4*)&Ws[k][tx * 4];
            ull b0, b1, b2, b3;
            PACK_F32X2(b0, Bv.x, Bv.x); PACK_F32X2(b1, Bv.y, Bv.y);
            PACK_F32X2(b2, Bv.z, Bv.z); PACK_F32X2(b3, Bv.w, Bv.w);
            FMA_F32X2(acc[0][0], A01.x, b0); FMA_F32X2(acc[0][1], A01.x, b1);
            FMA_F32X2(acc[0][2], A01.x, b2); FMA_F32X2(acc[0][3], A01.x, b3);
            FMA_F32X2(acc[1][0], A01.y, b0); FMA_F32X2(acc[1][1], A01.y, b1);
            FMA_F32X2(acc[1][2], A01.y, b2); FMA_F32X2(acc[1][3], A01.y, b3);
            FMA_F32X2(acc[2][0], A23.x, b0); FMA_F32X2(acc[2][1], A23.x, b1);
            FMA_F32X2(acc[2][2], A23.x, b2); FMA_F32X2(acc[2][3], A23.x, b3);
            FMA_F32X2(acc[3][0], A23.y, b0); FMA_F32X2(acc[3][1], A23.y, b1);
            FMA_F32X2(acc[3][2], A23.y, b2); FMA_F32X2(acc[3][3], A23.y, b3);
        }
        __syncthreads();
    }

    // epilogue
    if (tid < 128) s_stat[tid] = 0.f;
    __syncthreads();

    const float4 bia = *(const float4*)(bias + fbase + tx * 4);
    float sums[4] = {0.f, 0.f, 0.f, 0.f}, sqs[4] = {0.f, 0.f, 0.f, 0.f};

#pragma unroll
    for (int p = 0; p < 4; p++) {
        float l0, h0, l1, h1, l2, h2, l3, h3;
        UNPACK_F32X2(l0, h0, acc[p][0]);
        UNPACK_F32X2(l1, h1, acc[p][1]);
        UNPACK_F32X2(l2, h2, acc[p][2]);
        UNPACK_F32X2(l3, h3, acc[p][3]);
#pragma unroll
        for (int s = 0; s < 2; s++) {
            float e0 = s ? h0 : l0, e1 = s ? h1 : l1;
            float e2 = s ? h2 : l2, e3 = s ? h3 : l3;
            int nm = row0 + ty * 8 + 2 * p + s;
            if (nm >= NM_TOT) continue;
            int n = nm / 12;
            int j = g_idx32[nm];
            float msk = (j != 0) ? 1.f : 0.f;
            int col = fbase + tx * 4;
            float4 s4 = *(const float4*)(g_SA + (size_t)n * 512 + col);
            float4 a4 = *(const float4*)(g_SA + (size_t)j * 512 + 256 + col);
            float g0 = s4.x + bia.x + msk * (a4.x + e0);
            float g1 = s4.y + bia.y + msk * (a4.y + e1);
            float g2 = s4.z + bia.z + msk * (a4.z + e2);
            float g3 = s4.w + bia.w + msk * (a4.w + e3);
            *(float4*)(g_gated + (size_t)nm * 256 + col) = make_float4(g0, g1, g2, g3);
            sums[0] += g0; sqs[0] += g0 * g0;
            sums[1] += g1; sqs[1] += g1 * g1;
            sums[2] += g2; sqs[2] += g2 * g2;
            sums[3] += g3; sqs[3] += g3 * g3;
        }
    }
#pragma unroll
    for (int c = 0; c < 4; c++) {
        int lc = tx * 4 + c;
        atomicAdd(&s_stat[lc], sums[c]);
        atomicAdd(&s_stat[64 + lc], sqs[c]);
    }
    __syncthreads();
    if (tid < 64) {
        atomicAdd(&g_stats1[fbase + tid],       s_stat[tid]);
        atomicAdd(&g_stats1[256 + fbase + tid], s_stat[64 + tid]);
    }
}

// ---------------- k3: finalize BN1 affine ------------------------------------
__global__ void k_fin1(const float* __restrict__ gamma1, const float* __restrict__ beta1) {
    int f = threadIdx.x;  // 256
    float inv = 1.f / (float)NM_TOT;
    float mean = g_stats1[f] * inv;
    float var  = g_stats1[256 + f] * inv - mean * mean;
    float sc = gamma1[f] * rsqrtf(var + EPS);
    g_bn1[f] = sc;
    g_bn1[256 + f] = beta1[f] - mean * sc;
}

// ---------------- k4: gate + sum over M + BN2 stats --------------------------
__global__ __launch_bounds__(128) void k_reduce() {
    const int f = threadIdx.x;
    const int n0 = blockIdx.x * CH;
    const float sc_f = g_bn1[f],        sh_f = g_bn1[256 + f];
    const float sc_c = g_bn1[128 + f],  sh_c = g_bn1[256 + 128 + f];
    float bs = 0.f, bq = 0.f;
    for (int n = n0; n < n0 + CH; n++) {
        float acc = 0.f;
#pragma unroll
        for (int m = 0; m < 12; m++) {
            int nm = n * 12 + m;
            int j = g_idx32[nm];
            if (j != 0) {
                float gf = g_gated[(size_t)nm * 256 + f]       * sc_f + sh_f;
                float gc = g_gated[(size_t)nm * 256 + 128 + f] * sc_c + sh_c;
                acc += sigmoidf(gf) * softplusf(gc);
            }
        }
        g_nbr[(size_t)n * 128 + f] = acc;
        bs += acc; bq += acc * acc;
    }
    atomicAdd(&g_stats2[f],       bs);
    atomicAdd(&g_stats2[128 + f], bq);
}

// ---------------- k5: finalize BN2 affine ------------------------------------
__global__ void k_fin2(const float* __restrict__ gamma2, const float* __restrict__ beta2) {
    int f = threadIdx.x;  // 128
    float inv = 1.f / (float)N_ATOM;
    float mean = g_stats2[f] * inv;
    float var  = g_stats2[128 + f] * inv - mean * mean;
    float sc = gamma2[f] * rsqrtf(var + EPS);
    g_bn2[f] = sc;
    g_bn2[128 + f] = beta2[f] - mean * sc;
}

// ---------------- k6: out = softplus(atom + BN2(nbr_sumed)) ------------------
__global__ void k_out(const float* __restrict__ atom, float* __restrict__ out) {
    int i = blockIdx.x * blockDim.x + threadIdx.x;
    if (i < N_ATOM * 128) {
        int f = i & 127;
        float v = atom[i] + g_nbr[i] * g_bn2[f] + g_bn2[128 + f];
        out[i] = softplusf(v);
    }
}

// ---------------- launch ------------------------------------------------------
extern "C" void kernel_launch(void* const* d_in, const int* in_sizes, int n_in,
                              void* d_out, int out_size) {
    const float* atom   = (const float*)d_in[0];
    const float* nbr    = (const float*)d_in[1];
    const int*   idxraw = (const int*)d_in[2];
    const float* W      = (const float*)d_in[3];
    const float* b      = (const float*)d_in[4];
    const float* gamma1 = (const float*)d_in[5];
    const float* beta1  = (const float*)d_in[6];
    const float* gamma2 = (const float*)d_in[7];
    const float* beta2  = (const float*)d_in[8];
    float* out = (float*)d_out;

    k_detect<<<1, 256>>>(idxraw);
    k_convert<<<(NM_TOT + 255) / 256, 256>>>(idxraw);
    k_gemm_sa<<<dim3(4, (N_ATOM + 63) / 64), 256>>>(atom, W);
    k_gemm_gate<<<dim3(4, (NM_TOT + 127) / 128), 256>>>(nbr, W, b);
    k_fin1<<<1, 256>>>(gamma1, beta1);
    k_reduce<<<N_ATOM / CH, 128>>>();
    k_fin2<<<1, 128>>>(gamma2, beta2);
    k_out<<<(N_ATOM * 128 + 255) / 256, 256>>>(atom, out);
}